// round 2
// baseline (speedup 1.0000x reference)
#include <cuda_runtime.h>
#include <cuda_bf16.h>

// BALayer association: 16-hop min-label propagation + rank compaction.
// Equivalent to the reference's A^16 nonzero-pattern "leading index" labeling:
//   leading[j] = min node index within graph distance <= n_img of j
//   point_id   = cumsum(leading == id) - 1
//   out[j]     = point_id[leading[j]]
//
// Inputs (metadata order):
//   d_in[0] proj_mats  (F*9 f32)      -- unused
//   d_in[1] feats      (F*C*H*W f32)  -- unused
//   d_in[2] feat_img   (N i32)        -- only N = in_sizes[2] used
//   d_in[3] feat_loc   (N*2 f32)      -- unused
//   d_in[4] tracks     (2*M i32)      -- edge list, row0 = u[0..M), row1 = v[0..M)
//   d_in[5] n_img      (1 i32)        -- iteration count (16), if passed
// Output: association (N elements, written as float32 values of the int ids)

#define NTHREADS 1024
#define EMAX 8  // register-cached edges per thread (covers M <= 8192)

__global__ __launch_bounds__(NTHREADS, 1)
void ba_assoc_kernel(const int* __restrict__ tracks, int M,
                     const int* __restrict__ n_img_ptr,
                     float* __restrict__ out, int N)
{
    extern __shared__ int sm[];
    int* cur  = sm;          // N labels
    int* nxt  = sm + N;      // N labels (double buffer)
    int* scan = sm + 2 * N;  // NTHREADS/32 warp sums

    const int tid = threadIdx.x;
    const int nt  = blockDim.x;
    const int* __restrict__ t0 = tracks;
    const int* __restrict__ t1 = tracks + M;

    // Init labels: label[i] = i
    for (int i = tid; i < N; i += nt) cur[i] = i;

    // Cache this thread's edges in registers
    int eu[EMAX], ev[EMAX];
    int ne = 0;
    const bool cached = (M <= nt * EMAX);
    if (cached) {
        int m = tid;
        #pragma unroll
        for (int k = 0; k < EMAX; k++) {
            if (m < M) { eu[k] = t0[m]; ev[k] = t1[m]; ne++; m += nt; }
        }
    }

    const int iters = n_img_ptr ? *n_img_ptr : 16;
    __syncthreads();

    // Synchronous (Jacobi) min-label propagation, exactly `iters` rounds.
    // After k rounds, cur[j] = min node index within distance <= k of j
    // == min over the nonzero pattern of column j of A^k (A has unit diag).
    for (int it = 0; it < iters; ++it) {
        for (int i = tid; i < N; i += nt) nxt[i] = cur[i];
        __syncthreads();

        if (cached) {
            #pragma unroll
            for (int k = 0; k < EMAX; k++) {
                if (k < ne) {
                    const int u = eu[k], v = ev[k];
                    const int lu = cur[u], lv = cur[v];
                    if (lv < lu) atomicMin(&nxt[u], lv);
                    else if (lu < lv) atomicMin(&nxt[v], lu);
                }
            }
        } else {
            for (int m = tid; m < M; m += nt) {
                const int u = t0[m], v = t1[m];
                const int lu = cur[u], lv = cur[v];
                if (lv < lu) atomicMin(&nxt[u], lv);
                else if (lu < lv) atomicMin(&nxt[v], lu);
            }
        }
        __syncthreads();
        int* tmp = cur; cur = nxt; nxt = tmp;
    }

    // cur[j] = leading[j]. Compute point_id[i] = (#self-leading <= i) - 1 for
    // ALL i (matches jnp.cumsum semantics), then gather through leading.
    const int per  = (N + nt - 1) / nt;
    const int base = tid * per;
    int cnt = 0;
    for (int k = 0; k < per; k++) {
        const int i = base + k;
        if (i < N) cnt += (cur[i] == i);
    }

    const int lane = tid & 31;
    const int wid  = tid >> 5;
    int x = cnt;
    #pragma unroll
    for (int o = 1; o < 32; o <<= 1) {
        int y = __shfl_up_sync(0xFFFFFFFFu, x, o);
        if (lane >= o) x += y;
    }
    if (lane == 31) scan[wid] = x;   // inclusive warp total
    __syncthreads();
    if (wid == 0) {
        const int nwarps = nt >> 5;
        int w = (tid < nwarps) ? scan[tid] : 0;
        #pragma unroll
        for (int o = 1; o < 32; o <<= 1) {
            int y = __shfl_up_sync(0xFFFFFFFFu, w, o);
            if (lane >= o) w += y;
        }
        if (tid < nwarps) scan[tid] = w;  // inclusive scan of warp totals
    }
    __syncthreads();

    // Exclusive prefix for this thread's chunk
    int run = (x - cnt) + (wid ? scan[wid - 1] : 0);

    // point_id into nxt
    for (int k = 0; k < per; k++) {
        const int i = base + k;
        if (i < N) {
            run += (cur[i] == i);
            nxt[i] = run - 1;
        }
    }
    __syncthreads();

    // association[j] = point_id[leading[j]], written as float32 values
    for (int i = tid; i < N; i += nt) out[i] = (float)nxt[cur[i]];
}

extern "C" void kernel_launch(void* const* d_in, const int* in_sizes, int n_in,
                              void* d_out, int out_size)
{
    const int* tracks = (const int*)d_in[4];
    const int  M      = in_sizes[4] / 2;
    const int  N      = in_sizes[2];           // feat_img has N elements
    const int* n_img  = (n_in >= 6 && in_sizes[5] == 1) ? (const int*)d_in[5]
                                                        : nullptr;
    float* out = (float*)d_out;

    const size_t shbytes = (size_t)(2 * N + (NTHREADS / 32)) * sizeof(int);
    ba_assoc_kernel<<<1, NTHREADS, shbytes>>>(tracks, M, n_img, out, N);
}

// round 3
// speedup vs baseline: 1.1937x; 1.1937x over previous
#include <cuda_runtime.h>
#include <cuda_bf16.h>

// BALayer association: n_img-hop min-label propagation + rank compaction.
// Exactly matches the reference's A^n_img nonzero-pattern "leading index":
//   leading[j] = min node index within graph distance <= n_img of j
//   point_id   = cumsum(leading == id) - 1
//   out[j]     = point_id[leading[j]]   (written as float32)
//
// Jacobi rounds with early exit: labels are monotone non-increasing, so a
// round with zero changes is a fixed point -> remaining rounds are identity
// and exiting early is bit-exact.
//
// Inputs (metadata order):
//   d_in[2] feat_img (N i32)  -- only N = in_sizes[2] used
//   d_in[4] tracks   (2*M i32) -- row0 = u[0..M), row1 = v[0..M)
//   d_in[5] n_img    (1 i32)   -- iteration count, if passed (else 16)

#define NTHREADS 1024
#define EMAX 8  // register-cached edges per thread (covers M <= 8192)

__global__ __launch_bounds__(NTHREADS, 1)
void ba_assoc_kernel(const int* __restrict__ tracks, int M,
                     const int* __restrict__ n_img_ptr,
                     float* __restrict__ out, int N)
{
    extern __shared__ int sm[];
    int* cur  = sm;          // N labels
    int* nxt  = sm + N;      // N labels (double buffer)
    int* scan = sm + 2 * N;  // NTHREADS/32 warp sums

    const int tid = threadIdx.x;
    const int nt  = blockDim.x;
    const int* __restrict__ t0 = tracks;
    const int* __restrict__ t1 = tracks + M;

    // Init labels: label[i] = i
    for (int i = tid; i < N; i += nt) cur[i] = i;

    // Cache this thread's edges in registers
    int eu[EMAX], ev[EMAX];
    int ne = 0;
    const bool cached = (M <= nt * EMAX);
    if (cached) {
        int m = tid;
        #pragma unroll
        for (int k = 0; k < EMAX; k++) {
            if (m < M) { eu[k] = t0[m]; ev[k] = t1[m]; ne++; m += nt; }
        }
    }

    const int iters = n_img_ptr ? *n_img_ptr : 16;
    // Can this block copy labels as one int4 per thread?
    const bool vec4 = (N == 4 * nt) && ((N & 3) == 0);
    __syncthreads();

    // Synchronous (Jacobi) min-label propagation, at most `iters` rounds,
    // early-exit once a round produces no change (fixed point).
    for (int it = 0; it < iters; ++it) {
        if (vec4) {
            reinterpret_cast<int4*>(nxt)[tid] = reinterpret_cast<const int4*>(cur)[tid];
        } else {
            for (int i = tid; i < N; i += nt) nxt[i] = cur[i];
        }
        __syncthreads();

        int changed = 0;
        if (cached) {
            #pragma unroll
            for (int k = 0; k < EMAX; k++) {
                if (k < ne) {
                    const int u = eu[k], v = ev[k];
                    const int lu = cur[u], lv = cur[v];
                    if (lv < lu) {
                        const int old = atomicMin(&nxt[u], lv);
                        changed |= (old > lv);
                    } else if (lu < lv) {
                        const int old = atomicMin(&nxt[v], lu);
                        changed |= (old > lu);
                    }
                }
            }
        } else {
            for (int m = tid; m < M; m += nt) {
                const int u = t0[m], v = t1[m];
                const int lu = cur[u], lv = cur[v];
                if (lv < lu) {
                    const int old = atomicMin(&nxt[u], lv);
                    changed |= (old > lv);
                } else if (lu < lv) {
                    const int old = atomicMin(&nxt[v], lu);
                    changed |= (old > lu);
                }
            }
        }
        const int any = __syncthreads_or(changed);
        int* tmp = cur; cur = nxt; nxt = tmp;
        if (!any) break;  // fixed point: remaining rounds are identity
    }

    // cur[j] = leading[j]. point_id[i] = (#self-leading <= i) - 1 for ALL i
    // (matches jnp.cumsum semantics), then gather through leading.
    const int per  = (N + nt - 1) / nt;
    const int base = tid * per;
    int cnt = 0;
    for (int k = 0; k < per; k++) {
        const int i = base + k;
        if (i < N) cnt += (cur[i] == i);
    }

    const int lane = tid & 31;
    const int wid  = tid >> 5;
    int x = cnt;
    #pragma unroll
    for (int o = 1; o < 32; o <<= 1) {
        int y = __shfl_up_sync(0xFFFFFFFFu, x, o);
        if (lane >= o) x += y;
    }
    if (lane == 31) scan[wid] = x;   // inclusive warp total
    __syncthreads();
    if (wid == 0) {
        const int nwarps = nt >> 5;
        int w = (tid < nwarps) ? scan[tid] : 0;
        #pragma unroll
        for (int o = 1; o < 32; o <<= 1) {
            int y = __shfl_up_sync(0xFFFFFFFFu, w, o);
            if (lane >= o) w += y;
        }
        if (tid < nwarps) scan[tid] = w;  // inclusive scan of warp totals
    }
    __syncthreads();

    // Exclusive prefix for this thread's chunk
    int run = (x - cnt) + (wid ? scan[wid - 1] : 0);

    // point_id into nxt
    for (int k = 0; k < per; k++) {
        const int i = base + k;
        if (i < N) {
            run += (cur[i] == i);
            nxt[i] = run - 1;
        }
    }
    __syncthreads();

    // association[j] = point_id[leading[j]], written as float32 values
    for (int i = tid; i < N; i += nt) out[i] = (float)nxt[cur[i]];
}

extern "C" void kernel_launch(void* const* d_in, const int* in_sizes, int n_in,
                              void* d_out, int out_size)
{
    const int* tracks = (const int*)d_in[4];
    const int  M      = in_sizes[4] / 2;
    const int  N      = in_sizes[2];           // feat_img has N elements
    const int* n_img  = (n_in >= 6 && in_sizes[5] == 1) ? (const int*)d_in[5]
                                                        : nullptr;
    float* out = (float*)d_out;

    const size_t shbytes = (size_t)(2 * N + (NTHREADS / 32)) * sizeof(int);
    ba_assoc_kernel<<<1, NTHREADS, shbytes>>>(tracks, M, n_img, out, N);
}

// round 4
// speedup vs baseline: 1.5738x; 1.3185x over previous
#include <cuda_runtime.h>
#include <cuda_bf16.h>

// BALayer association: n_img-hop min-label propagation + rank compaction.
// Reference semantics: leading[j] = min node index within graph distance
// <= n_img of j (nonzero pattern of A^n_img, unit diagonal);
// point_id = cumsum(leading==id)-1; out[j] = point_id[leading[j]] (f32).
//
// Fast path: asynchronous in-place relaxation on packed (label<<6 | dist)
// words. atomicMin orders by label, then dist. Invariant: (L,d), d<63,
// implies node L is within d hops (each relax adds one hop to a valid
// bound; stale reads preserve it). Fixed point = component min with
// shortest-hop dist. Certificate: if max dist <= n_img everywhere, the
// fixed point equals the n_img-hop answer exactly. Otherwise fall back to
// exact synchronous Jacobi (double-buffered, n_img rounds, early exit).

#define NTHREADS 1024
#define EMAX 8          // register-cached edges per thread (M <= 8192)
#define DSHIFT 6        // dist bits
#define DMASK 63

__global__ __launch_bounds__(NTHREADS, 1)
void ba_assoc_kernel(const int* __restrict__ tracks, int M,
                     const int* __restrict__ n_img_ptr,
                     float* __restrict__ out, int N)
{
    extern __shared__ int sm[];
    int* cur  = sm;          // N packed labels (async) / labels (fallback)
    int* nxt  = sm + N;      // N labels, fallback double buffer + point_id
    int* scan = sm + 2 * N;  // NTHREADS/32 warp sums

    const int tid = threadIdx.x;
    const int nt  = blockDim.x;
    const int* __restrict__ t0 = tracks;
    const int* __restrict__ t1 = tracks + M;

    // Register-cache this thread's edges
    int eu[EMAX], ev[EMAX];
    int ne = 0;
    const bool cached = (M <= nt * EMAX);
    if (cached) {
        int m = tid;
        #pragma unroll
        for (int k = 0; k < EMAX; k++) {
            if (m < M) { eu[k] = t0[m]; ev[k] = t1[m]; ne++; m += nt; }
        }
    }
    const int iters = n_img_ptr ? *n_img_ptr : 16;

    // ---- Async phase: packed (label<<6 | dist), in-place relaxation ----
    for (int i = tid; i < N; i += nt) cur[i] = i << DSHIFT;  // dist 0
    __syncthreads();

    for (;;) {
        int changed = 0;
        if (cached) {
            #pragma unroll
            for (int k = 0; k < EMAX; k++) {
                if (k < ne) {
                    const int u = eu[k], v = ev[k];
                    const int pu = cur[u], pv = cur[v];
                    // candidate from v to u: same label, dist+1 (saturate 63)
                    const int cv = pv + (int)((pv & DMASK) != DMASK);
                    const int cu = pu + (int)((pu & DMASK) != DMASK);
                    if (cv < pu) {
                        const int old = atomicMin(&cur[u], cv);
                        changed |= (old > cv);
                    } else if (cu < pv) {
                        const int old = atomicMin(&cur[v], cu);
                        changed |= (old > cu);
                    }
                }
            }
        } else {
            for (int m = tid; m < M; m += nt) {
                const int u = t0[m], v = t1[m];
                const int pu = cur[u], pv = cur[v];
                const int cv = pv + (int)((pv & DMASK) != DMASK);
                const int cu = pu + (int)((pu & DMASK) != DMASK);
                if (cv < pu) {
                    const int old = atomicMin(&cur[u], cv);
                    changed |= (old > cv);
                } else if (cu < pv) {
                    const int old = atomicMin(&cur[v], cu);
                    changed |= (old > cu);
                }
            }
        }
        if (!__syncthreads_or(changed)) break;  // fixed point
    }

    // Certificate: every node's component-min is within `iters` hops?
    int bad = 0;
    for (int i = tid; i < N; i += nt) bad |= ((cur[i] & DMASK) > iters);
    const int cert_fail = __syncthreads_or(bad);

    if (!cert_fail) {
        // Unpack labels in place (all threads synced after syncthreads_or)
        for (int i = tid; i < N; i += nt) cur[i] >>= DSHIFT;
        __syncthreads();
    } else {
        // ---- Exact fallback: synchronous Jacobi, `iters` rounds ----
        for (int i = tid; i < N; i += nt) cur[i] = i;
        __syncthreads();
        for (int it = 0; it < iters; ++it) {
            for (int i = tid; i < N; i += nt) nxt[i] = cur[i];
            __syncthreads();
            int changed = 0;
            for (int m = tid; m < M; m += nt) {
                const int u = t0[m], v = t1[m];
                const int lu = cur[u], lv = cur[v];
                if (lv < lu) {
                    const int old = atomicMin(&nxt[u], lv);
                    changed |= (old > lv);
                } else if (lu < lv) {
                    const int old = atomicMin(&nxt[v], lu);
                    changed |= (old > lu);
                }
            }
            const int any = __syncthreads_or(changed);
            int* tmp = cur; cur = nxt; nxt = tmp;
            if (!any) break;
        }
    }

    // ---- cur[j] = leading[j]. point_id over ALL indices, then gather ----
    const int per  = (N + nt - 1) / nt;
    const int base = tid * per;
    int cnt = 0;
    for (int k = 0; k < per; k++) {
        const int i = base + k;
        if (i < N) cnt += (cur[i] == i);
    }

    const int lane = tid & 31;
    const int wid  = tid >> 5;
    int x = cnt;
    #pragma unroll
    for (int o = 1; o < 32; o <<= 1) {
        int y = __shfl_up_sync(0xFFFFFFFFu, x, o);
        if (lane >= o) x += y;
    }
    if (lane == 31) scan[wid] = x;
    __syncthreads();
    if (wid == 0) {
        const int nwarps = nt >> 5;
        int w = (tid < nwarps) ? scan[tid] : 0;
        #pragma unroll
        for (int o = 1; o < 32; o <<= 1) {
            int y = __shfl_up_sync(0xFFFFFFFFu, w, o);
            if (lane >= o) w += y;
        }
        if (tid < nwarps) scan[tid] = w;
    }
    __syncthreads();

    int run = (x - cnt) + (wid ? scan[wid - 1] : 0);
    for (int k = 0; k < per; k++) {
        const int i = base + k;
        if (i < N) {
            run += (cur[i] == i);
            nxt[i] = run - 1;     // point_id
        }
    }
    __syncthreads();

    for (int i = tid; i < N; i += nt) out[i] = (float)nxt[cur[i]];
}

extern "C" void kernel_launch(void* const* d_in, const int* in_sizes, int n_in,
                              void* d_out, int out_size)
{
    const int* tracks = (const int*)d_in[4];
    const int  M      = in_sizes[4] / 2;
    const int  N      = in_sizes[2];
    const int* n_img  = (n_in >= 6 && in_sizes[5] == 1) ? (const int*)d_in[5]
                                                        : nullptr;
    float* out = (float*)d_out;

    const size_t shbytes = (size_t)(2 * N + (NTHREADS / 32)) * sizeof(int);
    ba_assoc_kernel<<<1, NTHREADS, shbytes>>>(tracks, M, n_img, out, N);
}